// round 1
// baseline (speedup 1.0000x reference)
#include <cuda_runtime.h>

// RoI bilinear pooling:
//   feat: (1, H=200, W=200, C=1024) fp32
//   rois: (N=300, 4) int32  [x0, y0, w, h]
//   out : (N, 7, 7, C) fp32
//
// One CTA per (roi, py, px) cell; 256 threads, one float4 (4 channels) each.
// All four source-pixel rows are C*4 = 4096B aligned -> perfectly coalesced
// 128B transactions per warp. Kernel is pure HBM streaming.

#define POOL  7
#define FH    200
#define FW    200
#define FC    1024
#define VEC   (FC / 4)   // 256 float4 per pixel row

__global__ __launch_bounds__(VEC, 8)
void roi_pool_kernel(const float* __restrict__ feat,
                     const int*   __restrict__ rois,
                     float*       __restrict__ out)
{
    const int cell = blockIdx.x;        // 0..48
    const int n    = blockIdx.y;        // roi index
    const int py   = cell / POOL;
    const int px   = cell - py * POOL;

    // rois row: x0, y0, w, h  (16B aligned -> single int4 load, broadcast via L1)
    const int4 r = __ldg(((const int4*)rois) + n);
    const int x0 = r.x, y0 = r.y, w = r.z, h = r.w;

    // Replicate reference math exactly (fp32).
    const float ry = (float)py * ((float)h / (float)POOL);
    const float rx = (float)px * ((float)w / (float)POOL);
    const int ylo = (int)floorf(ry);
    const int xlo = (int)floorf(rx);
    const float fy = ry - (float)ylo;
    const float fx = rx - (float)xlo;
    const int yhi = min(ylo + 1, h - 1);
    const int xhi = min(xlo + 1, w - 1);

    const int iy0 = min(max(y0 + ylo, 0), FH - 1);
    const int iy1 = min(max(y0 + yhi, 0), FH - 1);
    const int ix0 = min(max(x0 + xlo, 0), FW - 1);
    const int ix1 = min(max(x0 + xhi, 0), FW - 1);

    const float wx0 = 1.0f - fx, wx1 = fx;
    const float wy0 = 1.0f - fy, wy1 = fy;

    const float4* p00 = (const float4*)(feat + ((size_t)iy0 * FW + ix0) * FC);
    const float4* p01 = (const float4*)(feat + ((size_t)iy0 * FW + ix1) * FC);
    const float4* p10 = (const float4*)(feat + ((size_t)iy1 * FW + ix0) * FC);
    const float4* p11 = (const float4*)(feat + ((size_t)iy1 * FW + ix1) * FC);

    const int c = threadIdx.x;          // 0..255 float4 lanes

    const float4 a = __ldg(p00 + c);
    const float4 b = __ldg(p01 + c);
    const float4 g = __ldg(p10 + c);
    const float4 d = __ldg(p11 + c);

    float4 o;
    // top = a*wx0 + b*wx1 ; bot = g*wx0 + d*wx1 ; out = top*wy0 + bot*wy1
    o.x = (a.x * wx0 + b.x * wx1) * wy0 + (g.x * wx0 + d.x * wx1) * wy1;
    o.y = (a.y * wx0 + b.y * wx1) * wy0 + (g.y * wx0 + d.y * wx1) * wy1;
    o.z = (a.z * wx0 + b.z * wx1) * wy0 + (g.z * wx0 + d.z * wx1) * wy1;
    o.w = (a.w * wx0 + b.w * wx1) * wy0 + (g.w * wx0 + d.w * wx1) * wy1;

    float4* outv = (float4*)out;
    outv[((size_t)n * (POOL * POOL) + cell) * VEC + c] = o;
}

extern "C" void kernel_launch(void* const* d_in, const int* in_sizes, int n_in,
                              void* d_out, int out_size)
{
    const float* feat = (const float*)d_in[0];   // (1,200,200,1024) fp32
    const int*   rois = (const int*)d_in[1];     // (N,4) int32
    const int N = in_sizes[1] / 4;

    dim3 grid(POOL * POOL, N);
    roi_pool_kernel<<<grid, VEC>>>(feat, rois, (float*)d_out);
}

// round 3
// speedup vs baseline: 1.0896x; 1.0896x over previous
#include <cuda_runtime.h>

// RoI bilinear pooling:
//   feat: (1, H=200, W=200, C=1024) fp32
//   rois: (N=300, 4) int32  [x0, y0, w, h]
//   out : (N, 7, 7, C) fp32
//
// R2: 2 cells per CTA, software-pipelined. Each thread issues 8 independent
// LDG.128s (4 per cell) before any consumption, doubling per-thread MLP to
// hide DRAM latency (kernel is latency-bound: traffic already minimal).

#define POOL  7
#define FH    200
#define FW    200
#define FC    1024
#define VEC   (FC / 4)     // 256 float4 per pixel row
#define NCELL (POOL * POOL)
#define NPAIR ((NCELL + 1) / 2)   // 25

__device__ __forceinline__ void cell_setup(int cell, int x0, int y0, int w, int h,
                                           const float* __restrict__ feat,
                                           const float4** p00, const float4** p01,
                                           const float4** p10, const float4** p11,
                                           float* wx0, float* wx1,
                                           float* wy0, float* wy1)
{
    const int py = cell / POOL;
    const int px = cell - py * POOL;

    const float ry = (float)py * ((float)h / (float)POOL);
    const float rx = (float)px * ((float)w / (float)POOL);
    const int ylo = (int)floorf(ry);
    const int xlo = (int)floorf(rx);
    const float fy = ry - (float)ylo;
    const float fx = rx - (float)xlo;
    const int yhi = min(ylo + 1, h - 1);
    const int xhi = min(xlo + 1, w - 1);

    const int iy0 = min(max(y0 + ylo, 0), FH - 1);
    const int iy1 = min(max(y0 + yhi, 0), FH - 1);
    const int ix0 = min(max(x0 + xlo, 0), FW - 1);
    const int ix1 = min(max(x0 + xhi, 0), FW - 1);

    *wx1 = fx;  *wx0 = 1.0f - fx;
    *wy1 = fy;  *wy0 = 1.0f - fy;

    *p00 = (const float4*)(feat + ((size_t)iy0 * FW + ix0) * FC);
    *p01 = (const float4*)(feat + ((size_t)iy0 * FW + ix1) * FC);
    *p10 = (const float4*)(feat + ((size_t)iy1 * FW + ix0) * FC);
    *p11 = (const float4*)(feat + ((size_t)iy1 * FW + ix1) * FC);
}

__device__ __forceinline__ float4 lerp2d(float4 a, float4 b, float4 g, float4 d,
                                         float wx0, float wx1, float wy0, float wy1)
{
    float4 o;
    o.x = (a.x * wx0 + b.x * wx1) * wy0 + (g.x * wx0 + d.x * wx1) * wy1;
    o.y = (a.y * wx0 + b.y * wx1) * wy0 + (g.y * wx0 + d.y * wx1) * wy1;
    o.z = (a.z * wx0 + b.z * wx1) * wy0 + (g.z * wx0 + d.z * wx1) * wy1;
    o.w = (a.w * wx0 + b.w * wx1) * wy0 + (g.w * wx0 + d.w * wx1) * wy1;
    return o;
}

__global__ __launch_bounds__(VEC)
void roi_pool_kernel(const float* __restrict__ feat,
                     const int*   __restrict__ rois,
                     float*       __restrict__ out)
{
    const int pair = blockIdx.x;            // 0..24
    const int n    = blockIdx.y;            // roi index
    const int cellA = pair * 2;
    const bool hasB = (cellA + 1) < NCELL;
    const int cellB = hasB ? (cellA + 1) : cellA;

    const int4 r = __ldg(((const int4*)rois) + n);
    const int x0 = r.x, y0 = r.y, w = r.z, h = r.w;

    const float4 *a00, *a01, *a10, *a11;
    const float4 *b00, *b01, *b10, *b11;
    float awx0, awx1, awy0, awy1;
    float bwx0, bwx1, bwy0, bwy1;

    cell_setup(cellA, x0, y0, w, h, feat, &a00, &a01, &a10, &a11,
               &awx0, &awx1, &awy0, &awy1);
    cell_setup(cellB, x0, y0, w, h, feat, &b00, &b01, &b10, &b11,
               &bwx0, &bwx1, &bwy0, &bwy1);

    const int c = threadIdx.x;              // 0..255 float4 lanes

    // Issue all 8 loads before any use — 8-deep MLP per thread.
    const float4 va = __ldg(a00 + c);
    const float4 vb = __ldg(a01 + c);
    const float4 vg = __ldg(a10 + c);
    const float4 vd = __ldg(a11 + c);
    const float4 ua = __ldg(b00 + c);
    const float4 ub = __ldg(b01 + c);
    const float4 ug = __ldg(b10 + c);
    const float4 ud = __ldg(b11 + c);

    float4* outv = (float4*)out;
    const size_t base = (size_t)n * NCELL;

    // Compute+store A while B's loads are still in flight.
    outv[(base + cellA) * VEC + c] =
        lerp2d(va, vb, vg, vd, awx0, awx1, awy0, awy1);

    if (hasB) {
        outv[(base + cellB) * VEC + c] =
            lerp2d(ua, ub, ug, ud, bwx0, bwx1, bwy0, bwy1);
    }
}

extern "C" void kernel_launch(void* const* d_in, const int* in_sizes, int n_in,
                              void* d_out, int out_size)
{
    const float* feat = (const float*)d_in[0];   // (1,200,200,1024) fp32
    const int*   rois = (const int*)d_in[1];     // (N,4) int32
    const int N = in_sizes[1] / 4;

    dim3 grid(NPAIR, N);
    roi_pool_kernel<<<grid, VEC>>>(feat, rois, (float*)d_out);
}